// round 8
// baseline (speedup 1.0000x reference)
#include <cuda_runtime.h>
#include <cuda_fp16.h>
#include <stdint.h>

#define T_TOK 8192
#define HID   2048
#define FFN_S 4096
#define NE    8

#define BM 128
#define BN 64
#define BKT 64          // K per smem tile in halves (128B rows)
#define STAGES 4

#define SWZ(x) ((x) ^ (((x) >> 3) & 0x70))

// per-stage byte layouts (all 1024-aligned)
#define A_BYTES  (BM * 128)          // 16384
#define B_BYTES  (BN * 128)          // 8192
#define STG1_BYTES (A_BYTES + 2 * B_BYTES)   // 32768
#define STG2_BYTES (A_BYTES + B_BYTES)       // 24576
#define SMEM_G1 (STAGES * STG1_BYTES + 1024)
#define SMEM_G2 (STAGES * STG2_BYTES + 1024)

// ---------------- scratch (__device__ globals; no allocation allowed) -------
__device__ __half g_w1h[(size_t)NE * FFN_S * HID];
__device__ __half g_w3h[(size_t)NE * FFN_S * HID];
__device__ __half g_w2h[(size_t)NE * HID * FFN_S];
__device__ __half g_xh [(size_t)T_TOK * HID];
__device__ __half g_h  [(size_t)2 * T_TOK * FFN_S];
__device__ float  g_y  [(size_t)2 * T_TOK * HID];
__device__ float  g_cw [2 * T_TOK];
__device__ int    g_list[NE * T_TOK];
__device__ int    g_cnt[NE];

// ---------------- fp32 -> fp16 conversion -----------------------------------
__device__ __forceinline__ void cvt_body(const float* __restrict__ src,
                                         __half* __restrict__ dst, int n4) {
    int stride = gridDim.x * blockDim.x;
    __half2* d = (__half2*)dst;
    for (int i = blockIdx.x * blockDim.x + threadIdx.x; i < n4; i += stride) {
        float4 v = ((const float4*)src)[i];
        d[2 * i]     = __floats2half2_rn(v.x, v.y);
        d[2 * i + 1] = __floats2half2_rn(v.z, v.w);
    }
}
__global__ void cvt_w1_kernel(const float* __restrict__ s) { cvt_body(s, g_w1h, (int)(NE * (size_t)FFN_S * HID / 4)); }
__global__ void cvt_w3_kernel(const float* __restrict__ s) { cvt_body(s, g_w3h, (int)(NE * (size_t)FFN_S * HID / 4)); }
__global__ void cvt_w2_kernel(const float* __restrict__ s) { cvt_body(s, g_w2h, (int)(NE * (size_t)HID * FFN_S / 4)); }
__global__ void cvt_x_kernel (const float* __restrict__ s) { cvt_body(s, g_xh,  T_TOK * HID / 4); }

__global__ void zero_cnt_kernel() {
    if (threadIdx.x < NE) g_cnt[threadIdx.x] = 0;
}

// ---------------- router ------------------------------------------------------
__global__ void router_kernel(const float* __restrict__ x,
                              const float* __restrict__ gw,
                              float* __restrict__ out_logits) {
    int gwarp = (blockIdx.x * blockDim.x + threadIdx.x) >> 5;
    int lane = threadIdx.x & 31;
    if (gwarp >= T_TOK) return;
    const float* xr = x + (size_t)gwarp * HID;
    float acc[NE];
#pragma unroll
    for (int e = 0; e < NE; e++) acc[e] = 0.f;
    for (int i = lane; i < HID; i += 32) {
        float xv = xr[i];
#pragma unroll
        for (int e = 0; e < NE; e++) acc[e] = fmaf(xv, gw[e * HID + i], acc[e]);
    }
#pragma unroll
    for (int e = 0; e < NE; e++) {
#pragma unroll
        for (int o = 16; o; o >>= 1) acc[e] += __shfl_xor_sync(0xffffffffu, acc[e], o);
    }
    if (lane == 0) {
        int i1 = 0;
#pragma unroll
        for (int e = 1; e < NE; e++) if (acc[e] > acc[i1]) i1 = e;
        int i2 = (i1 == 0) ? 1 : 0;
#pragma unroll
        for (int e = 0; e < NE; e++) if (e != i1 && acc[e] > acc[i2]) i2 = e;
        float m = fmaxf(acc[i1], acc[i2]);
        float p1 = expf(acc[i1] - m), p2 = expf(acc[i2] - m);
        float inv = 1.f / (p1 + p2);
        g_cw[2 * gwarp]     = p1 * inv;
        g_cw[2 * gwarp + 1] = p2 * inv;
        int p0 = atomicAdd(&g_cnt[i1], 1);
        g_list[i1 * T_TOK + p0] = 2 * gwarp;
        int q0 = atomicAdd(&g_cnt[i2], 1);
        g_list[i2 * T_TOK + q0] = 2 * gwarp + 1;
#pragma unroll
        for (int e = 0; e < NE; e++) out_logits[(size_t)gwarp * NE + e] = acc[e];
    }
}

// ---------------- async copy / ldmatrix / mma helpers ------------------------
__device__ __forceinline__ void cp_async16(uint32_t saddr, const void* gmem, bool pred) {
    int sz = pred ? 16 : 0;
    asm volatile("cp.async.cg.shared.global [%0], [%1], 16, %2;\n"
                 :: "r"(saddr), "l"(gmem), "r"(sz));
}
__device__ __forceinline__ void cp_commit() { asm volatile("cp.async.commit_group;\n"); }
__device__ __forceinline__ void cp_wait2()  { asm volatile("cp.async.wait_group 2;\n"); }
__device__ __forceinline__ void cp_wait1()  { asm volatile("cp.async.wait_group 1;\n"); }
__device__ __forceinline__ void cp_wait0()  { asm volatile("cp.async.wait_group 0;\n"); }

__device__ __forceinline__ void ldsm_x4(uint32_t* r, uint32_t addr) {
    asm volatile("ldmatrix.sync.aligned.m8n8.x4.shared.b16 {%0,%1,%2,%3}, [%4];\n"
                 : "=r"(r[0]), "=r"(r[1]), "=r"(r[2]), "=r"(r[3]) : "r"(addr));
}

__device__ __forceinline__ void mma_m16n8k16(float* d, const uint32_t* a, const uint32_t* b) {
    asm volatile(
        "mma.sync.aligned.m16n8k16.row.col.f32.f16.f16.f32 "
        "{%0,%1,%2,%3}, {%4,%5,%6,%7}, {%8,%9}, {%0,%1,%2,%3};\n"
        : "+f"(d[0]), "+f"(d[1]), "+f"(d[2]), "+f"(d[3])
        : "r"(a[0]), "r"(a[1]), "r"(a[2]), "r"(a[3]), "r"(b[0]), "r"(b[1]));
}

// ---------------- GEMM1: h = silu(X w1^T) * (X w3^T), gathered rows ---------
// 128x64x64 stage, 256 threads, 8 warps (4m x 2n), 4-stage, frag double-buffer.
__global__ __launch_bounds__(256) void gemm1_kernel() {
    const int e = blockIdx.z;
    const int ne = g_cnt[e];
    if ((int)(blockIdx.x * BM) >= ne) return;

    extern __shared__ uint8_t dynsmem[];
    __shared__ int rowids[BM];

    const int tid = threadIdx.x;
    if (tid < BM) {
        int idx = blockIdx.x * BM + tid;
        rowids[tid] = (idx < ne) ? g_list[e * T_TOK + idx] : -1;
    }
    __syncthreads();

    uint32_t base = (uint32_t)__cvta_generic_to_shared(dynsmem);
    base = (base + 1023) & ~1023u;

    const int lane = tid & 31, warp = tid >> 5;
    const int wm = (warp >> 1) * 32, wn = (warp & 1) * 32;
    const int grp = lane >> 2, qp = lane & 3;

    // ldmatrix lane->row/k offsets
    const int a_row = ((lane >> 3) & 1) * 8 + (lane & 7);
    const int a_kof = (lane >> 4) * 8;
    const int b_row = (lane >> 4) * 8 + (lane & 7);
    const int b_kof = ((lane >> 3) & 1) * 8;

    float acc1[2][4][4], acc3[2][4][4];
#pragma unroll
    for (int mi = 0; mi < 2; mi++)
#pragma unroll
        for (int ni = 0; ni < 4; ni++)
#pragma unroll
            for (int r = 0; r < 4; r++) { acc1[mi][ni][r] = 0.f; acc3[mi][ni][r] = 0.f; }

    const __half* w1base = g_w1h + ((size_t)e * FFN_S + blockIdx.y * BN) * HID;
    const __half* w3base = g_w3h + ((size_t)e * FFN_S + blockIdx.y * BN) * HID;

    auto load_tile = [&](int t) {
        int st = t & (STAGES - 1);
        uint32_t ab  = base + st * STG1_BYTES;
        uint32_t b1b = ab + A_BYTES;
        uint32_t b3b = b1b + B_BYTES;
        int kk = t * BKT;
#pragma unroll
        for (int i = 0; i < 4; i++) {
            int c = tid + i * 256;
            int r = c >> 3, ch = (c & 7) * 8;
            int t2 = rowids[r];
            const __half* src = (t2 >= 0) ? g_xh + (size_t)(t2 >> 1) * HID + kk + ch : g_xh;
            cp_async16(ab + SWZ(r * 128 + ch * 2), src, t2 >= 0);
        }
#pragma unroll
        for (int i = 0; i < 2; i++) {
            int c = tid + i * 256;
            int r = c >> 3, ch = (c & 7) * 8;
            cp_async16(b1b + SWZ(r * 128 + ch * 2), w1base + (size_t)r * HID + kk + ch, true);
            cp_async16(b3b + SWZ(r * 128 + ch * 2), w3base + (size_t)r * HID + kk + ch, true);
        }
        cp_commit();
    };

    const int NT = HID / BKT;     // 32
    load_tile(0);
    load_tile(1);
    load_tile(2);

    for (int t = 0; t < NT; t++) {
        int rem = NT - 1 - t;
        if (rem >= 2) cp_wait2(); else if (rem == 1) cp_wait1(); else cp_wait0();
        __syncthreads();

        int st = t & (STAGES - 1);
        uint32_t ab  = base + st * STG1_BYTES;
        uint32_t b1b = ab + A_BYTES;
        uint32_t b3b = b1b + B_BYTES;

        uint32_t aF[2][2][4], b1F[2][2][4], b3F[2][2][4];
        auto load_frags = [&](int buf, int k0) {
#pragma unroll
            for (int mi = 0; mi < 2; mi++)
                ldsm_x4(aF[buf][mi], ab + SWZ((wm + mi * 16 + a_row) * 128 + (k0 + a_kof) * 2));
#pragma unroll
            for (int p = 0; p < 2; p++) {
                ldsm_x4(b1F[buf][p], b1b + SWZ((wn + p * 16 + b_row) * 128 + (k0 + b_kof) * 2));
                ldsm_x4(b3F[buf][p], b3b + SWZ((wn + p * 16 + b_row) * 128 + (k0 + b_kof) * 2));
            }
        };

        load_frags(0, 0);
        if (t + 3 < NT) load_tile(t + 3);

#pragma unroll
        for (int k0 = 0; k0 < BKT; k0 += 16) {
            int buf = (k0 >> 4) & 1;
            if (k0 + 16 < BKT) load_frags(buf ^ 1, k0 + 16);
#pragma unroll
            for (int mi = 0; mi < 2; mi++)
#pragma unroll
                for (int p = 0; p < 2; p++)
#pragma unroll
                    for (int j = 0; j < 2; j++) {
                        mma_m16n8k16(acc1[mi][2 * p + j], aF[buf][mi], &b1F[buf][p][2 * j]);
                        mma_m16n8k16(acc3[mi][2 * p + j], aF[buf][mi], &b3F[buf][p][2 * j]);
                    }
        }
    }

    const int colbase = blockIdx.y * BN + wn;
#pragma unroll
    for (int mi = 0; mi < 2; mi++) {
#pragma unroll
        for (int j = 0; j < 2; j++) {
            int r = wm + mi * 16 + grp + j * 8;
            int t2 = rowids[r];
            if (t2 < 0) continue;
            __half* hrow = g_h + (size_t)t2 * FFN_S;
#pragma unroll
            for (int ni = 0; ni < 4; ni++) {
                float h1a = acc1[mi][ni][j * 2], h1b = acc1[mi][ni][j * 2 + 1];
                float h3a = acc3[mi][ni][j * 2], h3b = acc3[mi][ni][j * 2 + 1];
                float va = h1a * h3a / (1.f + __expf(-h1a));
                float vb = h1b * h3b / (1.f + __expf(-h1b));
                *(__half2*)(hrow + colbase + ni * 8 + qp * 2) = __floats2half2_rn(va, vb);
            }
        }
    }
}

// ---------------- GEMM2: y = h w2^T ------------------------------------------
__global__ __launch_bounds__(256) void gemm2_kernel() {
    const int e = blockIdx.z;
    const int ne = g_cnt[e];
    if ((int)(blockIdx.x * BM) >= ne) return;

    extern __shared__ uint8_t dynsmem[];
    __shared__ int rowids[BM];

    const int tid = threadIdx.x;
    if (tid < BM) {
        int idx = blockIdx.x * BM + tid;
        rowids[tid] = (idx < ne) ? g_list[e * T_TOK + idx] : -1;
    }
    __syncthreads();

    uint32_t base = (uint32_t)__cvta_generic_to_shared(dynsmem);
    base = (base + 1023) & ~1023u;

    const int lane = tid & 31, warp = tid >> 5;
    const int wm = (warp >> 1) * 32, wn = (warp & 1) * 32;
    const int grp = lane >> 2, qp = lane & 3;

    const int a_row = ((lane >> 3) & 1) * 8 + (lane & 7);
    const int a_kof = (lane >> 4) * 8;
    const int b_row = (lane >> 4) * 8 + (lane & 7);
    const int b_kof = ((lane >> 3) & 1) * 8;

    float acc[2][4][4];
#pragma unroll
    for (int mi = 0; mi < 2; mi++)
#pragma unroll
        for (int ni = 0; ni < 4; ni++)
#pragma unroll
            for (int r = 0; r < 4; r++) acc[mi][ni][r] = 0.f;

    const __half* w2base = g_w2h + ((size_t)e * HID + blockIdx.y * BN) * FFN_S;

    auto load_tile = [&](int t) {
        int st = t & (STAGES - 1);
        uint32_t ab = base + st * STG2_BYTES;
        uint32_t bb = ab + A_BYTES;
        int kk = t * BKT;
#pragma unroll
        for (int i = 0; i < 4; i++) {
            int c = tid + i * 256;
            int r = c >> 3, ch = (c & 7) * 8;
            int t2 = rowids[r];
            const __half* src = (t2 >= 0) ? g_h + (size_t)t2 * FFN_S + kk + ch : g_h;
            cp_async16(ab + SWZ(r * 128 + ch * 2), src, t2 >= 0);
        }
#pragma unroll
        for (int i = 0; i < 2; i++) {
            int c = tid + i * 256;
            int r = c >> 3, ch = (c & 7) * 8;
            cp_async16(bb + SWZ(r * 128 + ch * 2), w2base + (size_t)r * FFN_S + kk + ch, true);
        }
        cp_commit();
    };

    const int NT = FFN_S / BKT;   // 64
    load_tile(0);
    load_tile(1);
    load_tile(2);

    for (int t = 0; t < NT; t++) {
        int rem = NT - 1 - t;
        if (rem >= 2) cp_wait2(); else if (rem == 1) cp_wait1(); else cp_wait0();
        __syncthreads();

        int st = t & (STAGES - 1);
        uint32_t ab = base + st * STG2_BYTES;
        uint32_t bb = ab + A_BYTES;

        uint32_t aF[2][2][4], bF[2][2][4];
        auto load_frags = [&](int buf, int k0) {
#pragma unroll
            for (int mi = 0; mi < 2; mi++)
                ldsm_x4(aF[buf][mi], ab + SWZ((wm + mi * 16 + a_row) * 128 + (k0 + a_kof) * 2));
#pragma unroll
            for (int p = 0; p < 2; p++)
                ldsm_x4(bF[buf][p], bb + SWZ((wn + p * 16 + b_row) * 128 + (k0 + b_kof) * 2));
        };

        load_frags(0, 0);
        if (t + 3 < NT) load_tile(t + 3);

#pragma unroll
        for (int k0 = 0; k0 < BKT; k0 += 16) {
            int buf = (k0 >> 4) & 1;
            if (k0 + 16 < BKT) load_frags(buf ^ 1, k0 + 16);
#pragma unroll
            for (int mi = 0; mi < 2; mi++)
#pragma unroll
                for (int p = 0; p < 2; p++)
#pragma unroll
                    for (int j = 0; j < 2; j++)
                        mma_m16n8k16(acc[mi][2 * p + j], aF[buf][mi], &bF[buf][p][2 * j]);
        }
    }

    const int colbase = blockIdx.y * BN + wn;
#pragma unroll
    for (int mi = 0; mi < 2; mi++) {
#pragma unroll
        for (int j = 0; j < 2; j++) {
            int r = wm + mi * 16 + grp + j * 8;
            int t2 = rowids[r];
            if (t2 < 0) continue;
            float* yrow = g_y + (size_t)t2 * HID;
#pragma unroll
            for (int ni = 0; ni < 4; ni++) {
                float2 v = make_float2(acc[mi][ni][j * 2], acc[mi][ni][j * 2 + 1]);
                *(float2*)(yrow + colbase + ni * 8 + qp * 2) = v;
            }
        }
    }
}

// ---------------- combine: out[t] = w0*y[2t] + w1*y[2t+1] --------------------
__global__ void combine_kernel(float* __restrict__ out) {
    int t = blockIdx.x;
    float w0 = g_cw[2 * t], w1 = g_cw[2 * t + 1];
    const float4* y0 = (const float4*)(g_y + (size_t)(2 * t) * HID);
    const float4* y1 = (const float4*)(g_y + (size_t)(2 * t + 1) * HID);
    float4* o = (float4*)(out + (size_t)t * HID);
    for (int j = threadIdx.x; j < HID / 4; j += blockDim.x) {
        float4 a = y0[j], b = y1[j];
        o[j] = make_float4(w0 * a.x + w1 * b.x, w0 * a.y + w1 * b.y,
                           w0 * a.z + w1 * b.z, w0 * a.w + w1 * b.w);
    }
}

// ---------------- launch ------------------------------------------------------
extern "C" void kernel_launch(void* const* d_in, const int* in_sizes, int n_in,
                              void* d_out, int out_size) {
    const float* x  = (const float*)d_in[0];
    const float* gw = (const float*)d_in[1];
    const float* w1 = (const float*)d_in[2];
    const float* w3 = (const float*)d_in[3];
    const float* w2 = (const float*)d_in[4];
    float* out = (float*)d_out;

    cudaFuncSetAttribute(gemm1_kernel, cudaFuncAttributeMaxDynamicSharedMemorySize, SMEM_G1);
    cudaFuncSetAttribute(gemm2_kernel, cudaFuncAttributeMaxDynamicSharedMemorySize, SMEM_G2);

    zero_cnt_kernel<<<1, 32>>>();
    cvt_w1_kernel<<<8192, 256>>>(w1);
    cvt_w3_kernel<<<8192, 256>>>(w3);
    cvt_w2_kernel<<<8192, 256>>>(w2);
    cvt_x_kernel<<<2048, 256>>>(x);
    router_kernel<<<1024, 256>>>(x, gw, out + (size_t)T_TOK * HID);
    gemm1_kernel<<<dim3(T_TOK / BM, FFN_S / BN, NE), 256, SMEM_G1>>>();
    gemm2_kernel<<<dim3(T_TOK / BM, HID / BN, NE), 256, SMEM_G2>>>();
    combine_kernel<<<T_TOK, 256>>>(out);
}

// round 9
// speedup vs baseline: 1.3237x; 1.3237x over previous
#include <cuda_runtime.h>
#include <cuda_fp16.h>
#include <stdint.h>

#define T_TOK 8192
#define HID   2048
#define FFN_S 4096
#define NE    8

#define BM 128
#define BN 64
#define BN2 128
#define BKT 64          // K per smem tile in halves (128B rows)
#define STAGES 3

#define SWZ(x) ((x) ^ (((x) >> 3) & 0x70))

// per-stage byte layouts (all 1024-aligned)
#define A_BYTES  (BM * 128)          // 16384
#define B_BYTES  (BN * 128)          // 8192
#define B2_BYTES (BN2 * 128)         // 16384
#define STG1_BYTES (A_BYTES + 2 * B_BYTES)   // 32768
#define STG2_BYTES (A_BYTES + B2_BYTES)      // 32768
#define SMEM_G1 (STAGES * STG1_BYTES + 1024)
#define SMEM_G2 (STAGES * STG2_BYTES + 1024)

// ---------------- scratch (__device__ globals; no allocation allowed) -------
__device__ __half g_w1h[(size_t)NE * FFN_S * HID];
__device__ __half g_w3h[(size_t)NE * FFN_S * HID];
__device__ __half g_w2h[(size_t)NE * HID * FFN_S];
__device__ __half g_xh [(size_t)T_TOK * HID];
__device__ __half g_h  [(size_t)2 * T_TOK * FFN_S];
__device__ float  g_y  [(size_t)2 * T_TOK * HID];
__device__ float  g_cw [2 * T_TOK];
__device__ int    g_list[NE * T_TOK];
__device__ int    g_cnt[NE];

// ---------------- fp32 -> fp16 conversion -----------------------------------
__device__ __forceinline__ void cvt_body(const float* __restrict__ src,
                                         __half* __restrict__ dst, int n4) {
    int stride = gridDim.x * blockDim.x;
    __half2* d = (__half2*)dst;
    for (int i = blockIdx.x * blockDim.x + threadIdx.x; i < n4; i += stride) {
        float4 v = ((const float4*)src)[i];
        d[2 * i]     = __floats2half2_rn(v.x, v.y);
        d[2 * i + 1] = __floats2half2_rn(v.z, v.w);
    }
}
__global__ void cvt_w1_kernel(const float* __restrict__ s) { cvt_body(s, g_w1h, (int)(NE * (size_t)FFN_S * HID / 4)); }
__global__ void cvt_w3_kernel(const float* __restrict__ s) { cvt_body(s, g_w3h, (int)(NE * (size_t)FFN_S * HID / 4)); }
__global__ void cvt_w2_kernel(const float* __restrict__ s) { cvt_body(s, g_w2h, (int)(NE * (size_t)HID * FFN_S / 4)); }
__global__ void cvt_x_kernel (const float* __restrict__ s) { cvt_body(s, g_xh,  T_TOK * HID / 4); }

__global__ void zero_cnt_kernel() {
    if (threadIdx.x < NE) g_cnt[threadIdx.x] = 0;
}

// ---------------- router ------------------------------------------------------
__global__ void router_kernel(const float* __restrict__ x,
                              const float* __restrict__ gw,
                              float* __restrict__ out_logits) {
    int gwarp = (blockIdx.x * blockDim.x + threadIdx.x) >> 5;
    int lane = threadIdx.x & 31;
    if (gwarp >= T_TOK) return;
    const float* xr = x + (size_t)gwarp * HID;
    float acc[NE];
#pragma unroll
    for (int e = 0; e < NE; e++) acc[e] = 0.f;
    for (int i = lane; i < HID; i += 32) {
        float xv = xr[i];
#pragma unroll
        for (int e = 0; e < NE; e++) acc[e] = fmaf(xv, gw[e * HID + i], acc[e]);
    }
#pragma unroll
    for (int e = 0; e < NE; e++) {
#pragma unroll
        for (int o = 16; o; o >>= 1) acc[e] += __shfl_xor_sync(0xffffffffu, acc[e], o);
    }
    if (lane == 0) {
        int i1 = 0;
#pragma unroll
        for (int e = 1; e < NE; e++) if (acc[e] > acc[i1]) i1 = e;
        int i2 = (i1 == 0) ? 1 : 0;
#pragma unroll
        for (int e = 0; e < NE; e++) if (e != i1 && acc[e] > acc[i2]) i2 = e;
        float m = fmaxf(acc[i1], acc[i2]);
        float p1 = expf(acc[i1] - m), p2 = expf(acc[i2] - m);
        float inv = 1.f / (p1 + p2);
        g_cw[2 * gwarp]     = p1 * inv;
        g_cw[2 * gwarp + 1] = p2 * inv;
        int p0 = atomicAdd(&g_cnt[i1], 1);
        g_list[i1 * T_TOK + p0] = 2 * gwarp;
        int q0 = atomicAdd(&g_cnt[i2], 1);
        g_list[i2 * T_TOK + q0] = 2 * gwarp + 1;
#pragma unroll
        for (int e = 0; e < NE; e++) out_logits[(size_t)gwarp * NE + e] = acc[e];
    }
}

// ---------------- async copy / ldmatrix / mma helpers ------------------------
__device__ __forceinline__ void cp_async16(uint32_t saddr, const void* gmem, bool pred) {
    int sz = pred ? 16 : 0;
    asm volatile("cp.async.cg.shared.global [%0], [%1], 16, %2;\n"
                 :: "r"(saddr), "l"(gmem), "r"(sz));
}
__device__ __forceinline__ void cp_commit() { asm volatile("cp.async.commit_group;\n"); }
__device__ __forceinline__ void cp_wait1()  { asm volatile("cp.async.wait_group 1;\n"); }
__device__ __forceinline__ void cp_wait0()  { asm volatile("cp.async.wait_group 0;\n"); }

__device__ __forceinline__ void ldsm_x4(uint32_t* r, uint32_t addr) {
    asm volatile("ldmatrix.sync.aligned.m8n8.x4.shared.b16 {%0,%1,%2,%3}, [%4];\n"
                 : "=r"(r[0]), "=r"(r[1]), "=r"(r[2]), "=r"(r[3]) : "r"(addr));
}

__device__ __forceinline__ void mma_m16n8k16(float* d, const uint32_t* a, const uint32_t* b) {
    asm volatile(
        "mma.sync.aligned.m16n8k16.row.col.f32.f16.f16.f32 "
        "{%0,%1,%2,%3}, {%4,%5,%6,%7}, {%8,%9}, {%0,%1,%2,%3};\n"
        : "+f"(d[0]), "+f"(d[1]), "+f"(d[2]), "+f"(d[3])
        : "r"(a[0]), "r"(a[1]), "r"(a[2]), "r"(a[3]), "r"(b[0]), "r"(b[1]));
}

// ---------------- GEMM1: h = silu(X w1^T) * (X w3^T), gathered rows ---------
// 128x64x64 stage, 256 threads, 8 warps (4m x 2n), 3-stage, 1 sync per tile.
__global__ __launch_bounds__(256, 2) void gemm1_kernel() {
    const int e = blockIdx.z;
    const int ne = g_cnt[e];
    if ((int)(blockIdx.x * BM) >= ne) return;

    extern __shared__ uint8_t dynsmem[];
    __shared__ int rowids[BM];

    const int tid = threadIdx.x;
    if (tid < BM) {
        int idx = blockIdx.x * BM + tid;
        rowids[tid] = (idx < ne) ? g_list[e * T_TOK + idx] : -1;
    }
    __syncthreads();

    uint32_t base = (uint32_t)__cvta_generic_to_shared(dynsmem);
    base = (base + 1023) & ~1023u;

    const int lane = tid & 31, warp = tid >> 5;
    const int wm = (warp >> 1) * 32, wn = (warp & 1) * 32;
    const int grp = lane >> 2, qp = lane & 3;

    // ldmatrix lane->row/k offsets
    const int a_row = ((lane >> 3) & 1) * 8 + (lane & 7);
    const int a_kof = (lane >> 4) * 8;
    const int b_row = (lane >> 4) * 8 + (lane & 7);
    const int b_kof = ((lane >> 3) & 1) * 8;

    float acc1[2][4][4], acc3[2][4][4];
#pragma unroll
    for (int mi = 0; mi < 2; mi++)
#pragma unroll
        for (int ni = 0; ni < 4; ni++)
#pragma unroll
            for (int r = 0; r < 4; r++) { acc1[mi][ni][r] = 0.f; acc3[mi][ni][r] = 0.f; }

    const __half* w1base = g_w1h + ((size_t)e * FFN_S + blockIdx.y * BN) * HID;
    const __half* w3base = g_w3h + ((size_t)e * FFN_S + blockIdx.y * BN) * HID;

    auto load_tile = [&](int t) {
        int st = t % STAGES;
        uint32_t ab  = base + st * STG1_BYTES;
        uint32_t b1b = ab + A_BYTES;
        uint32_t b3b = b1b + B_BYTES;
        int kk = t * BKT;
#pragma unroll
        for (int i = 0; i < 4; i++) {
            int c = tid + i * 256;
            int r = c >> 3, ch = (c & 7) * 8;      // ch in halves
            int t2 = rowids[r];
            const __half* src = (t2 >= 0) ? g_xh + (size_t)(t2 >> 1) * HID + kk + ch : g_xh;
            cp_async16(ab + SWZ(r * 128 + ch * 2), src, t2 >= 0);
        }
#pragma unroll
        for (int i = 0; i < 2; i++) {
            int c = tid + i * 256;
            int r = c >> 3, ch = (c & 7) * 8;
            cp_async16(b1b + SWZ(r * 128 + ch * 2), w1base + (size_t)r * HID + kk + ch, true);
            cp_async16(b3b + SWZ(r * 128 + ch * 2), w3base + (size_t)r * HID + kk + ch, true);
        }
        cp_commit();
    };

    const int NT = HID / BKT;     // 32
    load_tile(0);
    load_tile(1);

    for (int t = 0; t < NT; t++) {
        if (t + 1 < NT) cp_wait1(); else cp_wait0();
        __syncthreads();
        if (t + 2 < NT) load_tile(t + 2);

        int st = t % STAGES;
        uint32_t ab  = base + st * STG1_BYTES;
        uint32_t b1b = ab + A_BYTES;
        uint32_t b3b = b1b + B_BYTES;
#pragma unroll
        for (int k0 = 0; k0 < BKT; k0 += 16) {
            uint32_t a[2][4], b1[2][4], b3[2][4];
#pragma unroll
            for (int mi = 0; mi < 2; mi++)
                ldsm_x4(a[mi], ab + SWZ((wm + mi * 16 + a_row) * 128 + (k0 + a_kof) * 2));
#pragma unroll
            for (int p = 0; p < 2; p++) {
                ldsm_x4(b1[p], b1b + SWZ((wn + p * 16 + b_row) * 128 + (k0 + b_kof) * 2));
                ldsm_x4(b3[p], b3b + SWZ((wn + p * 16 + b_row) * 128 + (k0 + b_kof) * 2));
            }
#pragma unroll
            for (int mi = 0; mi < 2; mi++)
#pragma unroll
                for (int p = 0; p < 2; p++)
#pragma unroll
                    for (int j = 0; j < 2; j++) {
                        mma_m16n8k16(acc1[mi][2 * p + j], a[mi], &b1[p][2 * j]);
                        mma_m16n8k16(acc3[mi][2 * p + j], a[mi], &b3[p][2 * j]);
                    }
        }
    }

    const int colbase = blockIdx.y * BN + wn;
#pragma unroll
    for (int mi = 0; mi < 2; mi++) {
#pragma unroll
        for (int j = 0; j < 2; j++) {
            int r = wm + mi * 16 + grp + j * 8;
            int t2 = rowids[r];
            if (t2 < 0) continue;
            __half* hrow = g_h + (size_t)t2 * FFN_S;
#pragma unroll
            for (int ni = 0; ni < 4; ni++) {
                float h1a = acc1[mi][ni][j * 2], h1b = acc1[mi][ni][j * 2 + 1];
                float h3a = acc3[mi][ni][j * 2], h3b = acc3[mi][ni][j * 2 + 1];
                float va = h1a * h3a / (1.f + __expf(-h1a));
                float vb = h1b * h3b / (1.f + __expf(-h1b));
                *(__half2*)(hrow + colbase + ni * 8 + qp * 2) = __floats2half2_rn(va, vb);
            }
        }
    }
}

// ---------------- GEMM2: y = h w2^T  (128x128 tile, warp 32x64) --------------
__global__ __launch_bounds__(256, 2) void gemm2_kernel() {
    const int e = blockIdx.z;
    const int ne = g_cnt[e];
    if ((int)(blockIdx.x * BM) >= ne) return;

    extern __shared__ uint8_t dynsmem[];
    __shared__ int rowids[BM];

    const int tid = threadIdx.x;
    if (tid < BM) {
        int idx = blockIdx.x * BM + tid;
        rowids[tid] = (idx < ne) ? g_list[e * T_TOK + idx] : -1;
    }
    __syncthreads();

    uint32_t base = (uint32_t)__cvta_generic_to_shared(dynsmem);
    base = (base + 1023) & ~1023u;

    const int lane = tid & 31, warp = tid >> 5;
    const int wm = (warp >> 1) * 32, wn = (warp & 1) * 64;
    const int grp = lane >> 2, qp = lane & 3;

    const int a_row = ((lane >> 3) & 1) * 8 + (lane & 7);
    const int a_kof = (lane >> 4) * 8;
    const int b_row = (lane >> 4) * 8 + (lane & 7);
    const int b_kof = ((lane >> 3) & 1) * 8;

    float acc[2][8][4];
#pragma unroll
    for (int mi = 0; mi < 2; mi++)
#pragma unroll
        for (int ni = 0; ni < 8; ni++)
#pragma unroll
            for (int r = 0; r < 4; r++) acc[mi][ni][r] = 0.f;

    const __half* w2base = g_w2h + ((size_t)e * HID + blockIdx.y * BN2) * FFN_S;

    auto load_tile = [&](int t) {
        int st = t % STAGES;
        uint32_t ab = base + st * STG2_BYTES;
        uint32_t bb = ab + A_BYTES;
        int kk = t * BKT;
#pragma unroll
        for (int i = 0; i < 4; i++) {
            int c = tid + i * 256;
            int r = c >> 3, ch = (c & 7) * 8;
            int t2 = rowids[r];
            const __half* src = (t2 >= 0) ? g_h + (size_t)t2 * FFN_S + kk + ch : g_h;
            cp_async16(ab + SWZ(r * 128 + ch * 2), src, t2 >= 0);
        }
#pragma unroll
        for (int i = 0; i < 4; i++) {
            int c = tid + i * 256;
            int r = c >> 3, ch = (c & 7) * 8;
            cp_async16(bb + SWZ(r * 128 + ch * 2), w2base + (size_t)r * FFN_S + kk + ch, true);
        }
        cp_commit();
    };

    const int NT = FFN_S / BKT;   // 64
    load_tile(0);
    load_tile(1);

    for (int t = 0; t < NT; t++) {
        if (t + 1 < NT) cp_wait1(); else cp_wait0();
        __syncthreads();
        if (t + 2 < NT) load_tile(t + 2);

        int st = t % STAGES;
        uint32_t ab = base + st * STG2_BYTES;
        uint32_t bb = ab + A_BYTES;
#pragma unroll
        for (int k0 = 0; k0 < BKT; k0 += 16) {
            uint32_t a[2][4], b[4][4];
#pragma unroll
            for (int mi = 0; mi < 2; mi++)
                ldsm_x4(a[mi], ab + SWZ((wm + mi * 16 + a_row) * 128 + (k0 + a_kof) * 2));
#pragma unroll
            for (int p = 0; p < 4; p++)
                ldsm_x4(b[p], bb + SWZ((wn + p * 16 + b_row) * 128 + (k0 + b_kof) * 2));
#pragma unroll
            for (int mi = 0; mi < 2; mi++)
#pragma unroll
                for (int p = 0; p < 4; p++)
#pragma unroll
                    for (int j = 0; j < 2; j++)
                        mma_m16n8k16(acc[mi][2 * p + j], a[mi], &b[p][2 * j]);
        }
    }

    const int colbase = blockIdx.y * BN2 + wn;
#pragma unroll
    for (int mi = 0; mi < 2; mi++) {
#pragma unroll
        for (int j = 0; j < 2; j++) {
            int r = wm + mi * 16 + grp + j * 8;
            int t2 = rowids[r];
            if (t2 < 0) continue;
            float* yrow = g_y + (size_t)t2 * HID;
#pragma unroll
            for (int ni = 0; ni < 8; ni++) {
                float2 v = make_float2(acc[mi][ni][j * 2], acc[mi][ni][j * 2 + 1]);
                *(float2*)(yrow + colbase + ni * 8 + qp * 2) = v;
            }
        }
    }
}

// ---------------- combine: out[t] = w0*y[2t] + w1*y[2t+1] --------------------
__global__ void combine_kernel(float* __restrict__ out) {
    int t = blockIdx.x;
    float w0 = g_cw[2 * t], w1 = g_cw[2 * t + 1];
    const float4* y0 = (const float4*)(g_y + (size_t)(2 * t) * HID);
    const float4* y1 = (const float4*)(g_y + (size_t)(2 * t + 1) * HID);
    float4* o = (float4*)(out + (size_t)t * HID);
    for (int j = threadIdx.x; j < HID / 4; j += blockDim.x) {
        float4 a = y0[j], b = y1[j];
        o[j] = make_float4(w0 * a.x + w1 * b.x, w0 * a.y + w1 * b.y,
                           w0 * a.z + w1 * b.z, w0 * a.w + w1 * b.w);
    }
}

// ---------------- launch ------------------------------------------------------
extern "C" void kernel_launch(void* const* d_in, const int* in_sizes, int n_in,
                              void* d_out, int out_size) {
    const float* x  = (const float*)d_in[0];
    const float* gw = (const float*)d_in[1];
    const float* w1 = (const float*)d_in[2];
    const float* w3 = (const float*)d_in[3];
    const float* w2 = (const float*)d_in[4];
    float* out = (float*)d_out;

    cudaFuncSetAttribute(gemm1_kernel, cudaFuncAttributeMaxDynamicSharedMemorySize, SMEM_G1);
    cudaFuncSetAttribute(gemm2_kernel, cudaFuncAttributeMaxDynamicSharedMemorySize, SMEM_G2);

    zero_cnt_kernel<<<1, 32>>>();
    cvt_w1_kernel<<<8192, 256>>>(w1);
    cvt_w3_kernel<<<8192, 256>>>(w3);
    cvt_w2_kernel<<<8192, 256>>>(w2);
    cvt_x_kernel<<<2048, 256>>>(x);
    router_kernel<<<1024, 256>>>(x, gw, out + (size_t)T_TOK * HID);
    gemm1_kernel<<<dim3(T_TOK / BM, FFN_S / BN, NE), 256, SMEM_G1>>>();
    gemm2_kernel<<<dim3(T_TOK / BM, HID / BN2, NE), 256, SMEM_G2>>>();
    combine_kernel<<<T_TOK, 256>>>(out);
}

// round 13
// speedup vs baseline: 1.3330x; 1.0070x over previous
#include <cuda_runtime.h>
#include <cuda_fp16.h>
#include <stdint.h>

#define T_TOK 8192
#define HID   2048
#define FFN_S 4096
#define NE    8

#define BM 128
#define BN 64
#define BN2 128
#define BKT 64          // K per smem tile in halves (128B rows)
#define STAGES 3

#define SWZ(x) ((x) ^ (((x) >> 3) & 0x70))

// per-stage byte layouts (all 1024-aligned)
#define A_BYTES  (BM * 128)          // 16384
#define B_BYTES  (BN * 128)          // 8192
#define B2_BYTES (BN2 * 128)         // 16384
#define STG1_BYTES (A_BYTES + 2 * B_BYTES)   // 32768
#define STG2_BYTES (A_BYTES + B2_BYTES)      // 32768
#define SMEM_G1 (STAGES * STG1_BYTES + 1024)
#define SMEM_G2 (STAGES * STG2_BYTES + 1024)

// ---------------- scratch (__device__ globals; no allocation allowed) -------
__device__ __half g_w1h[(size_t)NE * FFN_S * HID];
__device__ __half g_w3h[(size_t)NE * FFN_S * HID];
__device__ __half g_w2h[(size_t)NE * HID * FFN_S];
__device__ __half g_xh [(size_t)T_TOK * HID];
__device__ __half g_h  [(size_t)2 * T_TOK * FFN_S];
__device__ float  g_y  [(size_t)2 * T_TOK * HID];
__device__ float  g_cw [2 * T_TOK];
__device__ int    g_list[NE * T_TOK];
__device__ int    g_cnt[NE];

// ---------------- fp32 -> fp16 conversion -----------------------------------
__device__ __forceinline__ void cvt_body(const float* __restrict__ src,
                                         __half* __restrict__ dst, int n4) {
    int stride = gridDim.x * blockDim.x;
    __half2* d = (__half2*)dst;
    for (int i = blockIdx.x * blockDim.x + threadIdx.x; i < n4; i += stride) {
        float4 v = ((const float4*)src)[i];
        d[2 * i]     = __floats2half2_rn(v.x, v.y);
        d[2 * i + 1] = __floats2half2_rn(v.z, v.w);
    }
}
__global__ void cvt_w1_kernel(const float* __restrict__ s) { cvt_body(s, g_w1h, (int)(NE * (size_t)FFN_S * HID / 4)); }
__global__ void cvt_w3_kernel(const float* __restrict__ s) { cvt_body(s, g_w3h, (int)(NE * (size_t)FFN_S * HID / 4)); }
__global__ void cvt_w2_kernel(const float* __restrict__ s) { cvt_body(s, g_w2h, (int)(NE * (size_t)HID * FFN_S / 4)); }
__global__ void cvt_x_kernel (const float* __restrict__ s) { cvt_body(s, g_xh,  T_TOK * HID / 4); }

__global__ void zero_cnt_kernel() {
    if (threadIdx.x < NE) g_cnt[threadIdx.x] = 0;
}

// ---------------- router ------------------------------------------------------
__global__ void router_kernel(const float* __restrict__ x,
                              const float* __restrict__ gw,
                              float* __restrict__ out_logits) {
    int gwarp = (blockIdx.x * blockDim.x + threadIdx.x) >> 5;
    int lane = threadIdx.x & 31;
    if (gwarp >= T_TOK) return;
    const float* xr = x + (size_t)gwarp * HID;
    float acc[NE];
#pragma unroll
    for (int e = 0; e < NE; e++) acc[e] = 0.f;
    for (int i = lane; i < HID; i += 32) {
        float xv = xr[i];
#pragma unroll
        for (int e = 0; e < NE; e++) acc[e] = fmaf(xv, gw[e * HID + i], acc[e]);
    }
#pragma unroll
    for (int e = 0; e < NE; e++) {
#pragma unroll
        for (int o = 16; o; o >>= 1) acc[e] += __shfl_xor_sync(0xffffffffu, acc[e], o);
    }
    if (lane == 0) {
        int i1 = 0;
#pragma unroll
        for (int e = 1; e < NE; e++) if (acc[e] > acc[i1]) i1 = e;
        int i2 = (i1 == 0) ? 1 : 0;
#pragma unroll
        for (int e = 0; e < NE; e++) if (e != i1 && acc[e] > acc[i2]) i2 = e;
        float m = fmaxf(acc[i1], acc[i2]);
        float p1 = expf(acc[i1] - m), p2 = expf(acc[i2] - m);
        float inv = 1.f / (p1 + p2);
        g_cw[2 * gwarp]     = p1 * inv;
        g_cw[2 * gwarp + 1] = p2 * inv;
        int p0 = atomicAdd(&g_cnt[i1], 1);
        g_list[i1 * T_TOK + p0] = 2 * gwarp;
        int q0 = atomicAdd(&g_cnt[i2], 1);
        g_list[i2 * T_TOK + q0] = 2 * gwarp + 1;
#pragma unroll
        for (int e = 0; e < NE; e++) out_logits[(size_t)gwarp * NE + e] = acc[e];
    }
}

// ---------------- async copy / ldmatrix / mma helpers ------------------------
__device__ __forceinline__ void cp_async16(uint32_t saddr, const void* gmem, bool pred) {
    int sz = pred ? 16 : 0;
    asm volatile("cp.async.cg.shared.global [%0], [%1], 16, %2;\n"
                 :: "r"(saddr), "l"(gmem), "r"(sz));
}
__device__ __forceinline__ void cp_commit() { asm volatile("cp.async.commit_group;\n"); }
__device__ __forceinline__ void cp_wait1()  { asm volatile("cp.async.wait_group 1;\n"); }
__device__ __forceinline__ void cp_wait0()  { asm volatile("cp.async.wait_group 0;\n"); }

__device__ __forceinline__ void ldsm_x4(uint32_t* r, uint32_t addr) {
    asm volatile("ldmatrix.sync.aligned.m8n8.x4.shared.b16 {%0,%1,%2,%3}, [%4];\n"
                 : "=r"(r[0]), "=r"(r[1]), "=r"(r[2]), "=r"(r[3]) : "r"(addr));
}

__device__ __forceinline__ void mma_m16n8k16(float* d, const uint32_t* a, const uint32_t* b) {
    asm volatile(
        "mma.sync.aligned.m16n8k16.row.col.f32.f16.f16.f32 "
        "{%0,%1,%2,%3}, {%4,%5,%6,%7}, {%8,%9}, {%0,%1,%2,%3};\n"
        : "+f"(d[0]), "+f"(d[1]), "+f"(d[2]), "+f"(d[3])
        : "r"(a[0]), "r"(a[1]), "r"(a[2]), "r"(a[3]), "r"(b[0]), "r"(b[1]));
}

// fast silu: x * sigmoid(x) with MUFU-only reciprocal (no div.rn sequence)
__device__ __forceinline__ float fast_silu_mul(float x, float m) {
    float u = __expf(-x);
    return __fdividef(x * m, 1.f + u);
}

// ---------------- GEMM1: h = silu(X w1^T) * (X w3^T), gathered rows ---------
// 128x64x64 stage, 256 threads, 8 warps (4m x 2n), 3-stage, 1 sync per tile.
__global__ __launch_bounds__(256, 2) void gemm1_kernel() {
    const int e = blockIdx.z;
    const int ne = g_cnt[e];
    if ((int)(blockIdx.x * BM) >= ne) return;

    extern __shared__ uint8_t dynsmem[];
    __shared__ int rowids[BM];

    const int tid = threadIdx.x;
    if (tid < BM) {
        int idx = blockIdx.x * BM + tid;
        rowids[tid] = (idx < ne) ? g_list[e * T_TOK + idx] : -1;
    }
    __syncthreads();

    uint32_t base = (uint32_t)__cvta_generic_to_shared(dynsmem);
    base = (base + 1023) & ~1023u;

    const int lane = tid & 31, warp = tid >> 5;
    const int wm = (warp >> 1) * 32, wn = (warp & 1) * 32;
    const int grp = lane >> 2, qp = lane & 3;

    // ldmatrix lane->row/k offsets
    const int a_row = ((lane >> 3) & 1) * 8 + (lane & 7);
    const int a_kof = (lane >> 4) * 8;
    const int b_row = (lane >> 4) * 8 + (lane & 7);
    const int b_kof = ((lane >> 3) & 1) * 8;

    float acc1[2][4][4], acc3[2][4][4];
#pragma unroll
    for (int mi = 0; mi < 2; mi++)
#pragma unroll
        for (int ni = 0; ni < 4; ni++)
#pragma unroll
            for (int r = 0; r < 4; r++) { acc1[mi][ni][r] = 0.f; acc3[mi][ni][r] = 0.f; }

    const __half* w1base = g_w1h + ((size_t)e * FFN_S + blockIdx.y * BN) * HID;
    const __half* w3base = g_w3h + ((size_t)e * FFN_S + blockIdx.y * BN) * HID;

    auto load_tile = [&](int t) {
        int st = t % STAGES;
        uint32_t ab  = base + st * STG1_BYTES;
        uint32_t b1b = ab + A_BYTES;
        uint32_t b3b = b1b + B_BYTES;
        int kk = t * BKT;
#pragma unroll
        for (int i = 0; i < 4; i++) {
            int c = tid + i * 256;
            int r = c >> 3, ch = (c & 7) * 8;      // ch in halves
            int t2 = rowids[r];
            const __half* src = (t2 >= 0) ? g_xh + (size_t)(t2 >> 1) * HID + kk + ch : g_xh;
            cp_async16(ab + SWZ(r * 128 + ch * 2), src, t2 >= 0);
        }
#pragma unroll
        for (int i = 0; i < 2; i++) {
            int c = tid + i * 256;
            int r = c >> 3, ch = (c & 7) * 8;
            cp_async16(b1b + SWZ(r * 128 + ch * 2), w1base + (size_t)r * HID + kk + ch, true);
            cp_async16(b3b + SWZ(r * 128 + ch * 2), w3base + (size_t)r * HID + kk + ch, true);
        }
        cp_commit();
    };

    const int NT = HID / BKT;     // 32
    load_tile(0);
    load_tile(1);

    for (int t = 0; t < NT; t++) {
        if (t + 1 < NT) cp_wait1(); else cp_wait0();
        __syncthreads();
        if (t + 2 < NT) load_tile(t + 2);

        int st = t % STAGES;
        uint32_t ab  = base + st * STG1_BYTES;
        uint32_t b1b = ab + A_BYTES;
        uint32_t b3b = b1b + B_BYTES;
#pragma unroll
        for (int k0 = 0; k0 < BKT; k0 += 16) {
            uint32_t a[2][4], b1[2][4], b3[2][4];
#pragma unroll
            for (int mi = 0; mi < 2; mi++)
                ldsm_x4(a[mi], ab + SWZ((wm + mi * 16 + a_row) * 128 + (k0 + a_kof) * 2));
#pragma unroll
            for (int p = 0; p < 2; p++) {
                ldsm_x4(b1[p], b1b + SWZ((wn + p * 16 + b_row) * 128 + (k0 + b_kof) * 2));
                ldsm_x4(b3[p], b3b + SWZ((wn + p * 16 + b_row) * 128 + (k0 + b_kof) * 2));
            }
#pragma unroll
            for (int mi = 0; mi < 2; mi++)
#pragma unroll
                for (int p = 0; p < 2; p++)
#pragma unroll
                    for (int j = 0; j < 2; j++) {
                        mma_m16n8k16(acc1[mi][2 * p + j], a[mi], &b1[p][2 * j]);
                        mma_m16n8k16(acc3[mi][2 * p + j], a[mi], &b3[p][2 * j]);
                    }
        }
    }

    const int colbase = blockIdx.y * BN + wn;
#pragma unroll
    for (int mi = 0; mi < 2; mi++) {
#pragma unroll
        for (int j = 0; j < 2; j++) {
            int r = wm + mi * 16 + grp + j * 8;
            int t2 = rowids[r];
            if (t2 < 0) continue;
            __half* hrow = g_h + (size_t)t2 * FFN_S;
#pragma unroll
            for (int ni = 0; ni < 4; ni++) {
                float h1a = acc1[mi][ni][j * 2], h1b = acc1[mi][ni][j * 2 + 1];
                float h3a = acc3[mi][ni][j * 2], h3b = acc3[mi][ni][j * 2 + 1];
                float va = fast_silu_mul(h1a, h3a);
                float vb = fast_silu_mul(h1b, h3b);
                *(__half2*)(hrow + colbase + ni * 8 + qp * 2) = __floats2half2_rn(va, vb);
            }
        }
    }
}

// ---------------- GEMM2: y = h w2^T  (128x128 tile, warp 32x64) --------------
__global__ __launch_bounds__(256, 2) void gemm2_kernel() {
    const int e = blockIdx.z;
    const int ne = g_cnt[e];
    if ((int)(blockIdx.x * BM) >= ne) return;

    extern __shared__ uint8_t dynsmem[];
    __shared__ int rowids[BM];

    const int tid = threadIdx.x;
    if (tid < BM) {
        int idx = blockIdx.x * BM + tid;
        rowids[tid] = (idx < ne) ? g_list[e * T_TOK + idx] : -1;
    }
    __syncthreads();

    uint32_t base = (uint32_t)__cvta_generic_to_shared(dynsmem);
    base = (base + 1023) & ~1023u;

    const int lane = tid & 31, warp = tid >> 5;
    const int wm = (warp >> 1) * 32, wn = (warp & 1) * 64;
    const int grp = lane >> 2, qp = lane & 3;

    const int a_row = ((lane >> 3) & 1) * 8 + (lane & 7);
    const int a_kof = (lane >> 4) * 8;
    const int b_row = (lane >> 4) * 8 + (lane & 7);
    const int b_kof = ((lane >> 3) & 1) * 8;

    float acc[2][8][4];
#pragma unroll
    for (int mi = 0; mi < 2; mi++)
#pragma unroll
        for (int ni = 0; ni < 8; ni++)
#pragma unroll
            for (int r = 0; r < 4; r++) acc[mi][ni][r] = 0.f;

    const __half* w2base = g_w2h + ((size_t)e * HID + blockIdx.y * BN2) * FFN_S;

    auto load_tile = [&](int t) {
        int st = t % STAGES;
        uint32_t ab = base + st * STG2_BYTES;
        uint32_t bb = ab + A_BYTES;
        int kk = t * BKT;
#pragma unroll
        for (int i = 0; i < 4; i++) {
            int c = tid + i * 256;
            int r = c >> 3, ch = (c & 7) * 8;
            int t2 = rowids[r];
            const __half* src = (t2 >= 0) ? g_h + (size_t)t2 * FFN_S + kk + ch : g_h;
            cp_async16(ab + SWZ(r * 128 + ch * 2), src, t2 >= 0);
        }
#pragma unroll
        for (int i = 0; i < 4; i++) {
            int c = tid + i * 256;
            int r = c >> 3, ch = (c & 7) * 8;
            cp_async16(bb + SWZ(r * 128 + ch * 2), w2base + (size_t)r * FFN_S + kk + ch, true);
        }
        cp_commit();
    };

    const int NT = FFN_S / BKT;   // 64
    load_tile(0);
    load_tile(1);

    for (int t = 0; t < NT; t++) {
        if (t + 1 < NT) cp_wait1(); else cp_wait0();
        __syncthreads();
        if (t + 2 < NT) load_tile(t + 2);

        int st = t % STAGES;
        uint32_t ab = base + st * STG2_BYTES;
        uint32_t bb = ab + A_BYTES;
#pragma unroll
        for (int k0 = 0; k0 < BKT; k0 += 16) {
            uint32_t a[2][4], b[4][4];
#pragma unroll
            for (int mi = 0; mi < 2; mi++)
                ldsm_x4(a[mi], ab + SWZ((wm + mi * 16 + a_row) * 128 + (k0 + a_kof) * 2));
#pragma unroll
            for (int p = 0; p < 4; p++)
                ldsm_x4(b[p], bb + SWZ((wn + p * 16 + b_row) * 128 + (k0 + b_kof) * 2));
#pragma unroll
            for (int mi = 0; mi < 2; mi++)
#pragma unroll
                for (int p = 0; p < 4; p++)
#pragma unroll
                    for (int j = 0; j < 2; j++)
                        mma_m16n8k16(acc[mi][2 * p + j], a[mi], &b[p][2 * j]);
        }
    }

    const int colbase = blockIdx.y * BN2 + wn;
#pragma unroll
    for (int mi = 0; mi < 2; mi++) {
#pragma unroll
        for (int j = 0; j < 2; j++) {
            int r = wm + mi * 16 + grp + j * 8;
            int t2 = rowids[r];
            if (t2 < 0) continue;
            float* yrow = g_y + (size_t)t2 * HID;
#pragma unroll
            for (int ni = 0; ni < 8; ni++) {
                float2 v = make_float2(acc[mi][ni][j * 2], acc[mi][ni][j * 2 + 1]);
                *(float2*)(yrow + colbase + ni * 8 + qp * 2) = v;
            }
        }
    }
}

// ---------------- combine: out[t] = w0*y[2t] + w1*y[2t+1] --------------------
__global__ void combine_kernel(float* __restrict__ out) {
    int t = blockIdx.x;
    float w0 = g_cw[2 * t], w1 = g_cw[2 * t + 1];
    const float4* y0 = (const float4*)(g_y + (size_t)(2 * t) * HID);
    const float4* y1 = (const float4*)(g_y + (size_t)(2 * t + 1) * HID);
    float4* o = (float4*)(out + (size_t)t * HID);
    for (int j = threadIdx.x; j < HID / 4; j += blockDim.x) {
        float4 a = y0[j], b = y1[j];
        o[j] = make_float4(w0 * a.x + w1 * b.x, w0 * a.y + w1 * b.y,
                           w0 * a.z + w1 * b.z, w0 * a.w + w1 * b.w);
    }
}

// ---------------- launch ------------------------------------------------------
extern "C" void kernel_launch(void* const* d_in, const int* in_sizes, int n_in,
                              void* d_out, int out_size) {
    const float* x  = (const float*)d_in[0];
    const float* gw = (const float*)d_in[1];
    const float* w1 = (const float*)d_in[2];
    const float* w3 = (const float*)d_in[3];
    const float* w2 = (const float*)d_in[4];
    float* out = (float*)d_out;

    cudaFuncSetAttribute(gemm1_kernel, cudaFuncAttributeMaxDynamicSharedMemorySize, SMEM_G1);
    cudaFuncSetAttribute(gemm2_kernel, cudaFuncAttributeMaxDynamicSharedMemorySize, SMEM_G2);

    zero_cnt_kernel<<<1, 32>>>();
    cvt_w1_kernel<<<8192, 256>>>(w1);
    cvt_w3_kernel<<<8192, 256>>>(w3);
    cvt_w2_kernel<<<8192, 256>>>(w2);
    cvt_x_kernel<<<2048, 256>>>(x);
    router_kernel<<<1024, 256>>>(x, gw, out + (size_t)T_TOK * HID);
    gemm1_kernel<<<dim3(T_TOK / BM, FFN_S / BN, NE), 256, SMEM_G1>>>();
    gemm2_kernel<<<dim3(T_TOK / BM, HID / BN2, NE), 256, SMEM_G2>>>();
    combine_kernel<<<T_TOK, 256>>>(out);
}